// round 16
// baseline (speedup 1.0000x reference)
#include <cuda_runtime.h>
#include <stdint.h>

#define BB 2
#define NN 2048
#define TK 8
#define NF 64
#define NNODES (BB*NN)
#define NE (NNODES*TK)
#define NBLK 128
#define NT 512
#define SED 66
#define SA  66
#define SAA 68   // A-region row stride: multiple of 4 for float4 stores

// ---- smem layout (floats) ----
// E:        coords [0, 8192)
// P:        sw1@8192 sw2@8960 swq@13056 sb1@17152 sb2@17216 sbq@17280 sX@17344..21568
// R:        sh [0, 33792); weights sW2@33792 sW3@38912 sWA@44032 sw1r@49152
//           biases @49472/49536/49600/49664 .. 49728
// sA:       [33792, 51200)  (overlays R weights AFTER they are dead)
// S:        sWp@0 sWrs@4096 sAgg@16384 sEd@20608 .. 24832 ; reads sA
// D:        W1@0 W2@4096 b@4288 sHH@16384 sEd@20608
#define PB  8192
#define RB  33792
#define SAB 33792

// ---------------- packed-fp32 (FFMA2) helpers ----------------
#define FMA2(acc, a, b) \
    asm("fma.rn.f32x2 %0, %1, %2, %0;" : "+l"(acc) : "l"(a), "l"(b))
#define DUP2(d, v) \
    asm("mov.b64 %0, {%1, %1};" : "=l"(d) : "f"(v))
#define PACK2(d, lo, hi) \
    asm("mov.b64 %0, {%1, %2};" : "=l"(d) : "f"(lo), "f"(hi))
#define UNPK2(lo, hi, v) \
    asm("mov.b64 {%0, %1}, %2;" : "=f"(lo), "=f"(hi) : "l"(v))

// ---------------- cp.async helpers ----------------
__device__ __forceinline__ void cpasync16(float* dst_smem, const float* src) {
    unsigned saddr = (unsigned)__cvta_generic_to_shared(dst_smem);
    asm volatile("cp.async.ca.shared.global [%0], [%1], 16;"
                 :: "r"(saddr), "l"(src) : "memory");
}
#define CP_COMMIT() asm volatile("cp.async.commit_group;" ::: "memory")
#define CP_WAIT0()  asm volatile("cp.async.wait_group 0;" ::: "memory")

// ---------------- device scratch ----------------
__device__ int   g_send[NE];
__device__ float g_q[NNODES*NF];
__device__ float g_UV[NNODES*128];
__device__ float g_eff0[NNODES*NF];
__device__ float g_eff1[NNODES*NF];
__device__ unsigned g_bar_cnt = 0;
__device__ unsigned g_bar_gen = 0;

// mask dtype detection (mask[0] true in-dataset)
__device__ __forceinline__ unsigned char mask_elem(const unsigned char* p, int i) {
    unsigned w0 = *(const unsigned*)p;
    if (w0 == 0x01010101u) return p[i] != 0;
    if (w0 == 0x3f800000u) return ((const float*)p)[i] != 0.f;
    return ((const int*)p)[i] != 0;
}

// grid-wide barrier: all NBLK blocks wave-1 resident (NBLK <= 148 SMs).
__device__ __forceinline__ void grid_bar() {
    __threadfence();
    __syncthreads();
    if (threadIdx.x == 0) {
        volatile unsigned* genp = &g_bar_gen;
        unsigned gen = *genp;
        if (atomicInc(&g_bar_cnt, NBLK - 1) == NBLK - 1) {
            atomicAdd(&g_bar_gen, 1);
        } else {
            while (*genp == gen) { }
        }
    }
    __syncthreads();
    __threadfence();
}

// h-chunk store for rel phase (row private to a 4-thread quad)
__device__ __forceinline__ void rel_store_h(
    float* myrow, int cbase, const unsigned long long* acc2)
{
#pragma unroll
    for (int p = 0; p < 4; p++) {
        float a0,a1,a2,a3;
        UNPK2(a0, a1, acc2[2*p]);
        UNPK2(a2, a3, acc2[2*p+1]);
        a0 = fmaxf(a0, 0.f); a1 = fmaxf(a1, 0.f);
        a2 = fmaxf(a2, 0.f); a3 = fmaxf(a3, 0.f);
        float* dst = myrow + 2*cbase + 8*p;
        *(float4*)dst       = make_float4(a0, a0, a1, a1);
        *(float4*)(dst + 4) = make_float4(a2, a2, a3, a3);
    }
}

// UV' = sEd(dup,transposed eff) @ [Wr|Ws] -> g_UV. 1 node x 8 cols per thread.
// Software-pipelined; over-reads at r=64 land in adjacent smem arrays (safe).
__device__ __forceinline__ void uv_from_sEd(
    const float* sWrs, const float* sEd, int node0, int tid)
{
    int tc2 = tid & 15;   // 8 cols of 128
    int tn2 = tid >> 4;   // 0..31, one node
    unsigned long long acc[4] = {0ULL, 0ULL, 0ULL, 0ULL};
    unsigned long long ev = *(const unsigned long long*)&sEd[2*tn2];
    ulonglong2 wa = *(const ulonglong2*)&sWrs[tc2*12];
    ulonglong2 wb = *(const ulonglong2*)&sWrs[tc2*12 + 4];
#pragma unroll 8
    for (int r = 0; r < 64; r++) {
        unsigned long long nev =
            *(const unsigned long long*)&sEd[(r+1)*SED + 2*tn2];
        const float* wp = &sWrs[(r+1)*192 + tc2*12];
        ulonglong2 na = *(const ulonglong2*)(wp);
        ulonglong2 nb = *(const ulonglong2*)(wp + 4);
        FMA2(acc[0], wa.x, ev); FMA2(acc[1], wa.y, ev);
        FMA2(acc[2], wb.x, ev); FMA2(acc[3], wb.y, ev);
        ev = nev; wa = na; wb = nb;
    }
    int node = node0 + tn2;
    float x0,x1,x2,x3,x4,x5,x6,x7;
    UNPK2(x0,x1, acc[0]); UNPK2(x2,x3, acc[1]);
    UNPK2(x4,x5, acc[2]); UNPK2(x6,x7, acc[3]);
    float* dst = g_UV + (size_t)node*128 + tc2*8;
    *(float4*)dst       = make_float4(x0,x1,x2,x3);
    *(float4*)(dst + 4) = make_float4(x4,x5,x6,x7);
}

// =====================  THE persistent kernel  =====================
__global__ __launch_bounds__(NT, 1) void k_all(
    const float* __restrict__ states, const float* __restrict__ a_cur,
    const float* __restrict__ s_delta,
    const unsigned char* __restrict__ mask_raw,
    const unsigned char* __restrict__ tmask_raw,
    const float* __restrict__ pe_w1, const float* __restrict__ pe_b1,
    const float* __restrict__ pe_w2, const float* __restrict__ pe_b2,
    const float* __restrict__ re_w1, const float* __restrict__ re_b1,
    const float* __restrict__ re_w2, const float* __restrict__ re_b2,
    const float* __restrict__ re_w3, const float* __restrict__ re_b3,
    const float* __restrict__ rp_w,  const float* __restrict__ rp_b,
    const float* __restrict__ pp_w,  const float* __restrict__ pp_b,
    const float* __restrict__ pr_w1, const float* __restrict__ pr_b1,
    const float* __restrict__ pr_w2, const float* __restrict__ pr_b2,
    float* __restrict__ out)
{
    extern __shared__ float buf[];
    const int tid = threadIdx.x;
    const int node0 = blockIdx.x * 32;     // 32 owned nodes (same batch)
    const int bb = node0 >> 11;
    const int i0 = node0 & (NN-1);

    float* sA = buf + SAB;

    // ======== Prefetch P + R weights (completes behind phase E) ========
    {
        for (int t = tid; t < 192; t += NT)
            cpasync16(buf + PB + t*4, pe_w1 + t*4);
        for (int t = tid; t < 1024; t += NT) {
            cpasync16(buf + PB + 768  + t*4, pe_w2 + t*4);
            cpasync16(buf + PB + 4864 + t*4, pp_w  + t*4);
        }
        if (tid < 16) {
            cpasync16(buf + PB + 8960 + tid*4, pe_b1 + tid*4);
            cpasync16(buf + PB + 9024 + tid*4, pe_b2 + tid*4);
            cpasync16(buf + PB + 9088 + tid*4, pp_b  + tid*4);
        }
        // R weights, swizzled layout: (r, chunk) -> 64B contiguous blocks
        for (int t = tid; t < 256; t += NT) {
            int r = t >> 2, ch = t & 3;
            int doff = RB + r*80 + ch*20;
            int soff = r*64 + ch*16;
#pragma unroll
            for (int q = 0; q < 4; q++) {
                cpasync16(buf + doff + 4*q,         re_w2 + soff + 4*q);
                cpasync16(buf + doff + 5120 + 4*q,  re_w3 + soff + 4*q);
                cpasync16(buf + doff + 10240 + 4*q, rp_w  + soff + 4*q);
            }
        }
        for (int t = tid; t < 80; t += NT)
            cpasync16(buf + RB + 15360 + t*4, re_w1 + t*4);
        if (tid < 16) {
            cpasync16(buf + RB + 15680 + tid*4, re_b1 + tid*4);
            cpasync16(buf + RB + 15744 + tid*4, re_b2 + tid*4);
            cpasync16(buf + RB + 15808 + tid*4, re_b3 + tid*4);
            cpasync16(buf + RB + 15872 + tid*4, rp_b  + tid*4);
        }
        CP_COMMIT();
    }

    // ======== Phase E: edge construction (8-NN + threshold filter) ========
    // Sender mask folded into coordinates: masked senders shifted +3e4.
    {
        float4* s_st4 = (float4*)buf;                         // [0, 8192)
        const float* stb = states + (size_t)bb*NN*3;
        for (int t = tid; t < NN; t += NT) {
            const float* p = stb + t*3;
            float big = mask_elem(mask_raw, bb*NN + t) ? 0.f : 3e4f;
            s_st4[t] = make_float4(p[0]+big, p[1]+big, p[2]+big, 0.f);
        }
        __syncthreads();

        const float TH2 = 0.12f * 0.12f;
        int w = tid >> 5, lane = tid & 31;   // w in 0..15
#pragma unroll 1
        for (int sub = 0; sub < 2; sub++) {
            int i = i0 + sub*16 + w;
            int node = bb*NN + i;
            bool recv_ok = mask_elem(mask_raw, node) &&
                           !mask_elem(tmask_raw, node);

            unsigned long long keys[TK];
#pragma unroll
            for (int k = 0; k < TK; k++) keys[k] = ~0ULL;

            if (recv_ok) {
                float4 si = s_st4[i];
                unsigned long long curmax = ~0ULL; int maxslot = 0;
                for (int j = lane; j < NN; j += 32) {
                    float4 sj = s_st4[j];
                    float dx = si.x - sj.x;
                    float dy = si.y - sj.y;
                    float dz = si.z - sj.z;
                    float d2 = fmaf(dx, dx, fmaf(dy, dy, dz*dz));
                    if (d2 < TH2) {
                        unsigned long long key =
                            ((unsigned long long)__float_as_uint(d2) << 32) | (unsigned)j;
                        if (key < curmax) {
                            keys[maxslot] = key;
                            curmax = keys[0]; maxslot = 0;
#pragma unroll
                            for (int k = 1; k < TK; k++)
                                if (keys[k] > curmax) { curmax = keys[k]; maxslot = k; }
                        }
                    }
                }
            }
#pragma unroll 1
            for (int r = 0; r < TK; r++) {
                unsigned long long mymin = keys[0]; int mslot = 0;
#pragma unroll
                for (int k = 1; k < TK; k++)
                    if (keys[k] < mymin) { mymin = keys[k]; mslot = k; }
                unsigned long long v = mymin;
#pragma unroll
                for (int off = 16; off; off >>= 1) {
                    unsigned long long o = __shfl_down_sync(0xffffffffu, v, off);
                    if (o < v) v = o;
                }
                v = __shfl_sync(0xffffffffu, v, 0);
                if (v == mymin && v != ~0ULL) keys[mslot] = ~0ULL;
                if (lane == 0) {
                    int j = (int)(v & 0xffffffffULL);
                    bool valid = (v != ~0ULL);
                    g_send[node*TK + r] = valid ? j : -1;
                }
            }
        }
        CP_WAIT0();        // prefetched weights resident
        __syncthreads();
    }

    // ======== Phase P: particle encoder + hoisted q (transposed FMA2) ======
    {
        float* sw1 = buf + PB;          // 768
        float* sw2 = buf + PB + 768;    // 4096
        float* swq = buf + PB + 4864;   // 4096
        float* sb1 = buf + PB + 8960;
        float* sb2 = buf + PB + 9024;
        float* sbq = buf + PB + 9088;
        float* sX  = buf + PB + 9152;   // 64*66 = 4224
        if (tid < 384) {
            int n = tid & 31, r = tid >> 5;   // r 0..11
            int nn = (node0 + n) & (NN-1);
            float v = (r < 9) ? s_delta[((size_t)bb*9 + r)*NN + nn]
                              : a_cur[bb*NN + nn];
            *(float2*)&sX[r*66 + 2*n] = make_float2(v, v);
        }
        __syncthreads();

        int tc = tid & 15, tn = tid >> 4;   // 16 colgroups x 32 nodes
        int node = node0 + tn;
        unsigned long long acc[2];
        float hreg[4];

        // L1: 12 -> 64, relu
        PACK2(acc[0], sb1[tc*4],   sb1[tc*4+1]);
        PACK2(acc[1], sb1[tc*4+2], sb1[tc*4+3]);
#pragma unroll
        for (int r = 0; r < 12; r++) {
            unsigned long long ev = *(const unsigned long long*)&sX[r*66 + 2*tn];
            ulonglong2 w = *(const ulonglong2*)&sw1[r*64 + tc*4];
            FMA2(acc[0], w.x, ev); FMA2(acc[1], w.y, ev);
        }
        {
            float a0,a1,a2,a3; UNPK2(a0,a1,acc[0]); UNPK2(a2,a3,acc[1]);
            hreg[0]=fmaxf(a0,0.f); hreg[1]=fmaxf(a1,0.f);
            hreg[2]=fmaxf(a2,0.f); hreg[3]=fmaxf(a3,0.f);
        }
        __syncthreads();
#pragma unroll
        for (int p = 0; p < 4; p++)
            *(float2*)&sX[(tc*4+p)*66 + 2*tn] = make_float2(hreg[p], hreg[p]);
        __syncthreads();

        // L2: 64 -> 64, relu -> pe (g_eff0) + restage
        PACK2(acc[0], sb2[tc*4],   sb2[tc*4+1]);
        PACK2(acc[1], sb2[tc*4+2], sb2[tc*4+3]);
#pragma unroll 8
        for (int r = 0; r < 64; r++) {
            unsigned long long ev = *(const unsigned long long*)&sX[r*66 + 2*tn];
            ulonglong2 w = *(const ulonglong2*)&sw2[r*64 + tc*4];
            FMA2(acc[0], w.x, ev); FMA2(acc[1], w.y, ev);
        }
        {
            float a0,a1,a2,a3; UNPK2(a0,a1,acc[0]); UNPK2(a2,a3,acc[1]);
            hreg[0]=fmaxf(a0,0.f); hreg[1]=fmaxf(a1,0.f);
            hreg[2]=fmaxf(a2,0.f); hreg[3]=fmaxf(a3,0.f);
        }
        *(float4*)&g_eff0[(size_t)node*64 + tc*4] =
            make_float4(hreg[0], hreg[1], hreg[2], hreg[3]);
        __syncthreads();
#pragma unroll
        for (int p = 0; p < 4; p++)
            *(float2*)&sX[(tc*4+p)*66 + 2*tn] = make_float2(hreg[p], hreg[p]);
        __syncthreads();

        // L3: q = pe @ pp_w[0:64] + pp_b (no relu)
        PACK2(acc[0], sbq[tc*4],   sbq[tc*4+1]);
        PACK2(acc[1], sbq[tc*4+2], sbq[tc*4+3]);
#pragma unroll 8
        for (int r = 0; r < 64; r++) {
            unsigned long long ev = *(const unsigned long long*)&sX[r*66 + 2*tn];
            ulonglong2 w = *(const ulonglong2*)&swq[r*64 + tc*4];
            FMA2(acc[0], w.x, ev); FMA2(acc[1], w.y, ev);
        }
        {
            float a0,a1,a2,a3; UNPK2(a0,a1,acc[0]); UNPK2(a2,a3,acc[1]);
            *(float4*)&g_q[(size_t)node*64 + tc*4] = make_float4(a0,a1,a2,a3);
        }
        __syncthreads();
    }

    // ======== Phase R: relation encoder (4 thr/edge, 2 edges/thread) ======
    // Weights already resident (prefetched). sh at [0, 33792).
    {
        float* sh  = buf;
        float* sW2 = buf + RB;
        float* sW3 = buf + RB + 5120;
        float* sWA = buf + RB + 10240;
        float* sw1 = buf + RB + 15360;
        float* sb1 = buf + RB + 15680;
        float* sb2 = buf + RB + 15744;
        float* sb3 = buf + RB + 15808;
        float* sb4 = buf + RB + 15872;

        int el = tid >> 2, part = tid & 3, cbase = part*16;  // el 0..127
        float* row0 = &sh[el*132];
        float* row1 = &sh[(128+el)*132];
        int e0 = node0*TK + el;
        int e1 = e0 + 128;
        int n0 = e0 >> 3, n1 = e1 >> 3;
        int i0e = n0 & (NN-1), i1e = n1 & (NN-1);
        int j0 = g_send[e0], j1 = g_send[e1];
        int jj0 = j0 < 0 ? 0 : j0, jj1 = j1 < 0 ? 0 : j1;

        float rin0[5], rin1[5];
        rin0[0] = a_cur[bb*NN + i0e];  rin1[0] = a_cur[bb*NN + i1e];
        rin0[1] = a_cur[bb*NN + jj0];  rin1[1] = a_cur[bb*NN + jj1];
#pragma unroll
        for (int d = 0; d < 3; d++) {
            rin0[2+d] = states[((size_t)bb*NN + i0e)*3 + d]
                      - states[((size_t)bb*NN + jj0)*3 + d];
            rin1[2+d] = states[((size_t)bb*NN + i1e)*3 + d]
                      - states[((size_t)bb*NN + jj1)*3 + d];
        }

        unsigned long long a0r[8], a1r[8];
        // ---- L1: 5 -> 64 ----
#pragma unroll
        for (int p = 0; p < 8; p++) {
            PACK2(a0r[p], sb1[cbase + 2*p], sb1[cbase + 2*p + 1]);
            a1r[p] = a0r[p];
        }
#pragma unroll
        for (int r = 0; r < 5; r++) {
            unsigned long long x0; DUP2(x0, rin0[r]);
            unsigned long long x1; DUP2(x1, rin1[r]);
            const float* wp = &sw1[r*64 + cbase];
#pragma unroll
            for (int p = 0; p < 8; p++) {
                unsigned long long wv = *(const unsigned long long*)(wp + 2*p);
                FMA2(a0r[p], wv, x0);
                FMA2(a1r[p], wv, x1);
            }
        }
        __syncwarp();
        rel_store_h(row0, cbase, a0r);
        rel_store_h(row1, cbase, a1r);
        __syncwarp();

        // ---- L2 (re_w2,relu), L3 (re_w3,relu), L4 (rp_w[0:64]+rp_b) ----
#pragma unroll 1
        for (int L = 0; L < 3; L++) {
            const float* Wm = (L==0) ? sW2 : (L==1) ? sW3 : sWA;
            const float* Bm = (L==0) ? sb2 : (L==1) ? sb3 : sb4;
#pragma unroll
            for (int p = 0; p < 8; p++) {
                PACK2(a0r[p], Bm[cbase + 2*p], Bm[cbase + 2*p + 1]);
                a1r[p] = a0r[p];
            }
            unsigned long long hv0 = *(const unsigned long long*)(row0);
            unsigned long long hv1 = *(const unsigned long long*)(row1);
            const float* wp0 = &Wm[part*20];
            ulonglong2 wa = *(const ulonglong2*)(wp0);
            ulonglong2 wb = *(const ulonglong2*)(wp0 + 4);
            ulonglong2 wc = *(const ulonglong2*)(wp0 + 8);
            ulonglong2 wd = *(const ulonglong2*)(wp0 + 12);
#pragma unroll 8
            for (int r = 0; r < 64; r++) {
                unsigned long long nh0 =
                    *(const unsigned long long*)(row0 + 2*(r+1));
                unsigned long long nh1 =
                    *(const unsigned long long*)(row1 + 2*(r+1));
                const float* wp = &Wm[(r+1)*80 + part*20];
                ulonglong2 na = *(const ulonglong2*)(wp);
                ulonglong2 nb = *(const ulonglong2*)(wp + 4);
                ulonglong2 nc = *(const ulonglong2*)(wp + 8);
                ulonglong2 nd = *(const ulonglong2*)(wp + 12);
                FMA2(a0r[0], wa.x, hv0); FMA2(a0r[1], wa.y, hv0);
                FMA2(a0r[2], wb.x, hv0); FMA2(a0r[3], wb.y, hv0);
                FMA2(a0r[4], wc.x, hv0); FMA2(a0r[5], wc.y, hv0);
                FMA2(a0r[6], wd.x, hv0); FMA2(a0r[7], wd.y, hv0);
                FMA2(a1r[0], wa.x, hv1); FMA2(a1r[1], wa.y, hv1);
                FMA2(a1r[2], wb.x, hv1); FMA2(a1r[3], wb.y, hv1);
                FMA2(a1r[4], wc.x, hv1); FMA2(a1r[5], wc.y, hv1);
                FMA2(a1r[6], wd.x, hv1); FMA2(a1r[7], wd.y, hv1);
                hv0 = nh0; hv1 = nh1;
                wa = na; wb = nb; wc = nc; wd = nd;
            }
            if (L < 2) {
                __syncwarp();
                rel_store_h(row0, cbase, a0r);
                rel_store_h(row1, cbase, a1r);
                __syncwarp();
            } else {
                // all sh + weight reads done -> overlay A region (over weights)
                __syncthreads();
                float* dst0 = sA + (size_t)el*SAA + cbase;
                float* dst1 = sA + (size_t)(128+el)*SAA + cbase;
#pragma unroll
                for (int p = 0; p < 4; p++) {
                    float a0,a1,a2,a3;
                    UNPK2(a0, a1, a0r[2*p]);
                    UNPK2(a2, a3, a0r[2*p+1]);
                    if (j0 < 0) { a0 = a1 = a2 = a3 = 0.f; }
                    *(float4*)(dst0 + 4*p) = make_float4(a0, a1, a2, a3);
                    UNPK2(a0, a1, a1r[2*p]);
                    UNPK2(a2, a3, a1r[2*p+1]);
                    if (j1 < 0) { a0 = a1 = a2 = a3 = 0.f; }
                    *(float4*)(dst1 + 4*p) = make_float4(a0, a1, a2, a3);
                }
            }
        }
        __syncthreads();
    }

    // ======== Phase S: UV0 + 3 fused prop steps ========
    {
        float* sWp  = buf;            // 4096 (pp_w rows 64..127)
        float* sWrs = buf + 4096;     // 12288 ([Wr|Ws] chunk-padded)
        float* sAgg = buf + 16384;    // 64*SA = 4224
        float* sEd  = buf + 20608;    // 64*SED = 4224 -> end 24832
        for (int t = tid; t < 4096; t += NT) sWp[t] = pp_w[4096 + t];
        for (int t = tid; t < 8192; t += NT) {
            int r = t >> 7, c = t & 127;
            float v = (c < 64) ? rp_w[(size_t)(64+r)*64 + c]
                               : rp_w[(size_t)(128+r)*64 + (c-64)];
            sWrs[r*192 + (c>>3)*12 + (c&7)] = v;
        }
        // fill sEd from eff0 (own nodes), duplicated-transposed
        {
            int n = tid >> 4, cg = tid & 15;   // n 0..31, 4 cols each
            const float* src = g_eff0 + (size_t)(node0 + n)*64 + cg*4;
            float4 v = *(const float4*)src;
            int c = cg*4;
            *(float2*)&sEd[(c+0)*SED + 2*n] = make_float2(v.x, v.x);
            *(float2*)&sEd[(c+1)*SED + 2*n] = make_float2(v.y, v.y);
            *(float2*)&sEd[(c+2)*SED + 2*n] = make_float2(v.z, v.z);
            *(float2*)&sEd[(c+3)*SED + 2*n] = make_float2(v.w, v.w);
        }
        __syncthreads();
        uv_from_sEd(sWrs, sEd, node0, tid);   // UV0
        grid_bar();

#pragma unroll 1
        for (int s = 0; s < 3; s++) {
            const float* effin  = (s & 1) ? g_eff1 : g_eff0;
            float*       effout = (s & 1) ? g_eff0 : g_eff1;

            // --- A1: per-edge gather + relu-sum -> sAgg (batched, MLP 8) ---
            int w = tid >> 5, l = tid & 31;   // w 0..15
#pragma unroll 1
            for (int kk = 0; kk < 2; kk++) {
                int node = node0 + w*2 + kk;
                int nl = node - node0;
                int nl8 = nl * TK;
                int bN = bb * NN;
                int4 sj0 = *(const int4*)&g_send[node*TK];
                int4 sj1 = *(const int4*)&g_send[node*TK + 4];
                int js[TK] = {sj0.x, sj0.y, sj0.z, sj0.w,
                              sj1.x, sj1.y, sj1.z, sj1.w};
                float2 u = *(const float2*)&g_UV[(size_t)node*128 + 2*l];
                float2 av[TK], vv[TK];
#pragma unroll
                for (int k = 0; k < TK; k++) {
                    int jj = js[k] < 0 ? 0 : js[k];
                    av[k] = *(const float2*)&sA[(size_t)(nl8 + k)*SAA + 2*l];
                    vv[k] = *(const float2*)&g_UV[(size_t)(bN + jj)*128 + 64 + 2*l];
                }
                float s0 = 0.f, s1 = 0.f;
#pragma unroll
                for (int k = 0; k < TK; k++)
                    if (js[k] >= 0) {
                        s0 += fmaxf(av[k].x + u.x + vv[k].x, 0.f);
                        s1 += fmaxf(av[k].y + u.y + vv[k].y, 0.f);
                    }
                *(float2*)&sAgg[(2*l  )*SA + 2*nl] = make_float2(s0, s0);
                *(float2*)&sAgg[(2*l+1)*SA + 2*nl] = make_float2(s1, s1);
            }
            __syncthreads();

            // --- A2: effout = relu(effin + q + agg @ Wp1) ; refill sEd ---
            {
                int tc = tid & 31;   // 2 cols
                int tn = tid >> 5;   // 0..15, 2 nodes each
                unsigned long long acc[2] = {0ULL, 0ULL};
                unsigned long long wv =
                    *(const unsigned long long*)&sWp[tc*2];
                unsigned long long ev0 =
                    *(const unsigned long long*)&sAgg[tn*4];
                unsigned long long ev1 =
                    *(const unsigned long long*)&sAgg[tn*4 + 2];
#pragma unroll 8
                for (int r = 0; r < 64; r++) {
                    unsigned long long nw =
                        *(const unsigned long long*)&sWp[(r+1)*64 + tc*2];
                    unsigned long long n0 =
                        *(const unsigned long long*)&sAgg[(r+1)*SA + tn*4];
                    unsigned long long n1 =
                        *(const unsigned long long*)&sAgg[(r+1)*SA + tn*4 + 2];
                    FMA2(acc[0], wv, ev0);
                    FMA2(acc[1], wv, ev1);
                    wv = nw; ev0 = n0; ev1 = n1;
                }
#pragma unroll
                for (int m = 0; m < 2; m++) {
                    int node = node0 + tn*2 + m;
                    int nl = tn*2 + m;
                    float2 ein = *(const float2*)&effin[(size_t)node*64 + 2*tc];
                    float2 q2  = *(const float2*)&g_q  [(size_t)node*64 + 2*tc];
                    float o0, o1; UNPK2(o0, o1, acc[m]);
                    o0 = fmaxf(o0 + ein.x + q2.x, 0.f);
                    o1 = fmaxf(o1 + ein.y + q2.y, 0.f);
                    *(float2*)&effout[(size_t)node*64 + 2*tc] = make_float2(o0, o1);
                    *(float2*)&sEd[(2*tc  )*SED + 2*nl] = make_float2(o0, o0);
                    *(float2*)&sEd[(2*tc+1)*SED + 2*nl] = make_float2(o1, o1);
                }
            }
            if (s < 2) {
                __syncthreads();
                uv_from_sEd(sWrs, sEd, node0, tid);  // UV for next step
                grid_bar();
            }
        }
        __syncthreads();
    }

    // ======== Phase D: predictor + residual add (from sEd, FMA2) ========
    {
        float* W1   = buf;          // 4096
        float* W2   = buf + 4096;   // 192
        float* b1   = buf + 4288;   // 64
        float* b2   = buf + 4352;   // 4
        float* sHH  = buf + 16384;  // hh staging, stride SA
        float* sEd  = buf + 20608;  // final effect (dup transposed)
        for (int t = tid; t < 4096; t += NT) W1[t] = pr_w1[t];
        for (int t = tid; t < 192;  t += NT) W2[t] = pr_w2[t];
        if (tid < 64) b1[tid] = pr_b1[tid];
        if (tid < 3)  b2[tid] = pr_b2[tid];
        __syncthreads();

        // layer 1: hh = relu(eff @ W1 + b1); sHH[r*SA + n] = hh[n][r]
        {
            int tc = tid & 31;   // 2 cols
            int tn = tid >> 5;   // 0..15, 2 nodes each
#pragma unroll
            for (int m = 0; m < 2; m++) {
                int nl = tn*2 + m;
                unsigned long long acc;
                PACK2(acc, b1[2*tc], b1[2*tc+1]);
#pragma unroll 8
                for (int r = 0; r < 64; r++) {
                    unsigned long long wv =
                        *(const unsigned long long*)&W1[r*64 + tc*2];
                    unsigned long long ev =
                        *(const unsigned long long*)&sEd[r*SED + 2*nl];
                    FMA2(acc, wv, ev);
                }
                float o0, o1; UNPK2(o0, o1, acc);
                sHH[(2*tc  )*SA + nl] = fmaxf(o0, 0.f);
                sHH[(2*tc+1)*SA + nl] = fmaxf(o1, 0.f);
            }
        }
        __syncthreads();

        // layer 2: out = states + hh @ W2 + b2  (3 cols, 96 workers)
        if (tid < 96) {
            int n = tid / 3, c = tid % 3;
            float acc = b2[c];
#pragma unroll 16
            for (int r = 0; r < 64; r++)
                acc = fmaf(sHH[r*SA + n], W2[r*3 + c], acc);
            int node = node0 + n;
            out[(size_t)node*3 + c] = states[(size_t)node*3 + c] + acc;
        }
    }
}

// ---------------- launch ----------------
extern "C" void kernel_launch(void* const* d_in, const int* in_sizes, int n_in,
                              void* d_out, int out_size)
{
    const float* states  = (const float*)d_in[0];
    const float* a_cur   = (const float*)d_in[1];
    const float* s_delta = (const float*)d_in[2];
    const unsigned char* mask  = (const unsigned char*)d_in[3];
    const unsigned char* tmask = (const unsigned char*)d_in[4];
    int wbase = (n_in > 5 && in_sizes[5] == 1) ? 6 : 5;
    const float* pe_w1 = (const float*)d_in[wbase + 0];
    const float* pe_b1 = (const float*)d_in[wbase + 1];
    const float* pe_w2 = (const float*)d_in[wbase + 2];
    const float* pe_b2 = (const float*)d_in[wbase + 3];
    const float* re_w1 = (const float*)d_in[wbase + 4];
    const float* re_b1 = (const float*)d_in[wbase + 5];
    const float* re_w2 = (const float*)d_in[wbase + 6];
    const float* re_b2 = (const float*)d_in[wbase + 7];
    const float* re_w3 = (const float*)d_in[wbase + 8];
    const float* re_b3 = (const float*)d_in[wbase + 9];
    const float* rp_w  = (const float*)d_in[wbase + 10];
    const float* rp_b  = (const float*)d_in[wbase + 11];
    const float* pp_w  = (const float*)d_in[wbase + 12];
    const float* pp_b  = (const float*)d_in[wbase + 13];
    const float* pr_w1 = (const float*)d_in[wbase + 14];
    const float* pr_b1 = (const float*)d_in[wbase + 15];
    const float* pr_w2 = (const float*)d_in[wbase + 16];
    const float* pr_b2 = (const float*)d_in[wbase + 17];
    float* out = (float*)d_out;

    const int DSM = 51200 * 4;   // 204800 B (sA end)
    static int attr_done = 0;
    if (!attr_done) {
        cudaFuncSetAttribute(k_all, cudaFuncAttributeMaxDynamicSharedMemorySize, DSM);
        attr_done = 1;
    }

    k_all<<<NBLK, NT, DSM>>>(states, a_cur, s_delta, mask, tmask,
                             pe_w1, pe_b1, pe_w2, pe_b2,
                             re_w1, re_b1, re_w2, re_b2, re_w3, re_b3,
                             rp_w, rp_b, pp_w, pp_b,
                             pr_w1, pr_b1, pr_w2, pr_b2, out);
}

// round 17
// speedup vs baseline: 1.0142x; 1.0142x over previous
#include <cuda_runtime.h>
#include <stdint.h>

#define BB 2
#define NN 2048
#define TK 8
#define NF 64
#define NNODES (BB*NN)
#define NE (NNODES*TK)
#define NBLK 128
#define NT 512
#define SED 66
#define SA  66
#define SAA 68   // A-region row stride: multiple of 4 for float4 stores

// ---------------- packed-fp32 (FFMA2) helpers ----------------
#define FMA2(acc, a, b) \
    asm("fma.rn.f32x2 %0, %1, %2, %0;" : "+l"(acc) : "l"(a), "l"(b))
#define FMA2S(d, a, b, c) \
    asm("fma.rn.f32x2 %0, %1, %2, %3;" : "=l"(d) : "l"(a), "l"(b), "l"(c))
#define ADD2S(d, a, b) \
    asm("add.rn.f32x2 %0, %1, %2;" : "=l"(d) : "l"(a), "l"(b))
#define MUL2S(d, a, b) \
    asm("mul.rn.f32x2 %0, %1, %2;" : "=l"(d) : "l"(a), "l"(b))
#define DUP2(d, v) \
    asm("mov.b64 %0, {%1, %1};" : "=l"(d) : "f"(v))
#define PACK2(d, lo, hi) \
    asm("mov.b64 %0, {%1, %2};" : "=l"(d) : "f"(lo), "f"(hi))
#define UNPK2(lo, hi, v) \
    asm("mov.b64 {%0, %1}, %2;" : "=f"(lo), "=f"(hi) : "l"(v))

// ---------------- device scratch ----------------
__device__ int   g_send[NE];
__device__ float g_q[NNODES*NF];
__device__ float g_UV[NNODES*128];
__device__ float g_eff0[NNODES*NF];
__device__ float g_eff1[NNODES*NF];
__device__ unsigned g_bar_cnt = 0;
__device__ unsigned g_bar_gen = 0;

// mask dtype detection (mask[0] true in-dataset)
__device__ __forceinline__ unsigned char mask_elem(const unsigned char* p, int i) {
    unsigned w0 = *(const unsigned*)p;
    if (w0 == 0x01010101u) return p[i] != 0;
    if (w0 == 0x3f800000u) return ((const float*)p)[i] != 0.f;
    return ((const int*)p)[i] != 0;
}

// grid-wide barrier: all NBLK blocks wave-1 resident (NBLK <= 148 SMs).
__device__ __forceinline__ void grid_bar() {
    __threadfence();
    __syncthreads();
    if (threadIdx.x == 0) {
        volatile unsigned* genp = &g_bar_gen;
        unsigned gen = *genp;
        if (atomicInc(&g_bar_cnt, NBLK - 1) == NBLK - 1) {
            atomicAdd(&g_bar_gen, 1);
        } else {
            while (*genp == gen) { }
        }
    }
    __syncthreads();
    __threadfence();
}

// h-chunk store for rel phase (row private to a 4-thread quad)
__device__ __forceinline__ void rel_store_h(
    float* myrow, int cbase, const unsigned long long* acc2)
{
#pragma unroll
    for (int p = 0; p < 4; p++) {
        float a0,a1,a2,a3;
        UNPK2(a0, a1, acc2[2*p]);
        UNPK2(a2, a3, acc2[2*p+1]);
        a0 = fmaxf(a0, 0.f); a1 = fmaxf(a1, 0.f);
        a2 = fmaxf(a2, 0.f); a3 = fmaxf(a3, 0.f);
        float* dst = myrow + 2*cbase + 8*p;
        *(float4*)dst       = make_float4(a0, a0, a1, a1);
        *(float4*)(dst + 4) = make_float4(a2, a2, a3, a3);
    }
}

// UV' = sEd(dup,transposed eff) @ [Wr|Ws] -> g_UV. 1 node x 8 cols per thread.
// Software-pipelined; over-reads at r=64 land in adjacent smem arrays (safe).
__device__ __forceinline__ void uv_from_sEd(
    const float* sWrs, const float* sEd, int node0, int tid)
{
    int tc2 = tid & 15;   // 8 cols of 128
    int tn2 = tid >> 4;   // 0..31, one node
    unsigned long long acc[4] = {0ULL, 0ULL, 0ULL, 0ULL};
    unsigned long long ev = *(const unsigned long long*)&sEd[2*tn2];
    ulonglong2 wa = *(const ulonglong2*)&sWrs[tc2*12];
    ulonglong2 wb = *(const ulonglong2*)&sWrs[tc2*12 + 4];
#pragma unroll 8
    for (int r = 0; r < 64; r++) {
        unsigned long long nev =
            *(const unsigned long long*)&sEd[(r+1)*SED + 2*tn2];
        const float* wp = &sWrs[(r+1)*192 + tc2*12];
        ulonglong2 na = *(const ulonglong2*)(wp);
        ulonglong2 nb = *(const ulonglong2*)(wp + 4);
        FMA2(acc[0], wa.x, ev); FMA2(acc[1], wa.y, ev);
        FMA2(acc[2], wb.x, ev); FMA2(acc[3], wb.y, ev);
        ev = nev; wa = na; wb = nb;
    }
    int node = node0 + tn2;
    float x0,x1,x2,x3,x4,x5,x6,x7;
    UNPK2(x0,x1, acc[0]); UNPK2(x2,x3, acc[1]);
    UNPK2(x4,x5, acc[2]); UNPK2(x6,x7, acc[3]);
    float* dst = g_UV + (size_t)node*128 + tc2*8;
    *(float4*)dst       = make_float4(x0,x1,x2,x3);
    *(float4*)(dst + 4) = make_float4(x4,x5,x6,x7);
}

// =====================  THE persistent kernel  =====================
__global__ __launch_bounds__(NT, 1) void k_all(
    const float* __restrict__ states, const float* __restrict__ a_cur,
    const float* __restrict__ s_delta,
    const unsigned char* __restrict__ mask_raw,
    const unsigned char* __restrict__ tmask_raw,
    const float* __restrict__ pe_w1, const float* __restrict__ pe_b1,
    const float* __restrict__ pe_w2, const float* __restrict__ pe_b2,
    const float* __restrict__ re_w1, const float* __restrict__ re_b1,
    const float* __restrict__ re_w2, const float* __restrict__ re_b2,
    const float* __restrict__ re_w3, const float* __restrict__ re_b3,
    const float* __restrict__ rp_w,  const float* __restrict__ rp_b,
    const float* __restrict__ pp_w,  const float* __restrict__ pp_b,
    const float* __restrict__ pr_w1, const float* __restrict__ pr_b1,
    const float* __restrict__ pr_w2, const float* __restrict__ pr_b2,
    float* __restrict__ out)
{
    extern __shared__ float buf[];
    const int tid = threadIdx.x;
    const int node0 = blockIdx.x * 32;     // 32 owned nodes (same batch)
    const int bb = node0 >> 11;
    const int i0 = node0 & (NN-1);

    // persistent A region (written end of phase R, read in phase S):
    // buf[24832 .. 24832 + 256*SAA) = [24832, 42240) < 49728
    float* sA = buf + 24832;

    // ======== Phase E: 8-NN, SoA coords + packed f32x2 scan ========
    // Sender mask folded into coordinates: masked senders shifted +3e4 per
    // axis -> d2 ~ 2.7e9 >> TH2, never a valid edge.
    {
        float* sx = buf;            // 2048
        float* sy = buf + 2048;     // 2048
        float* sz = buf + 4096;     // 2048
        const float* stb = states + (size_t)bb*NN*3;
        for (int t = tid; t < NN; t += NT) {
            const float* p = stb + t*3;
            float big = mask_elem(mask_raw, bb*NN + t) ? 0.f : 3e4f;
            sx[t] = p[0] + big;
            sy[t] = p[1] + big;
            sz[t] = p[2] + big;
        }
        __syncthreads();

        const float TH2 = 0.12f * 0.12f;
        int w = tid >> 5, lane = tid & 31;   // w in 0..15
#pragma unroll 1
        for (int sub = 0; sub < 2; sub++) {
            int i = i0 + sub*16 + w;
            int node = bb*NN + i;
            bool recv_ok = mask_elem(mask_raw, node) &&
                           !mask_elem(tmask_raw, node);

            unsigned long long keys[TK];
#pragma unroll
            for (int k = 0; k < TK; k++) keys[k] = ~0ULL;

            if (recv_ok) {
                unsigned long long nxd, nyd, nzd;
                DUP2(nxd, -sx[i]); DUP2(nyd, -sy[i]); DUP2(nzd, -sz[i]);
                unsigned long long curmax = ~0ULL; int maxslot = 0;
#pragma unroll 1
                for (int it = 0; it < 32; it++) {
                    int j2 = 2*lane + it*64;
                    unsigned long long xj = *(const unsigned long long*)&sx[j2];
                    unsigned long long yj = *(const unsigned long long*)&sy[j2];
                    unsigned long long zj = *(const unsigned long long*)&sz[j2];
                    unsigned long long dx, dy, dz, d2p;
                    ADD2S(dx, xj, nxd);
                    ADD2S(dy, yj, nyd);
                    ADD2S(dz, zj, nzd);
                    MUL2S(d2p, dz, dz);
                    FMA2S(d2p, dy, dy, d2p);
                    FMA2S(d2p, dx, dx, d2p);
                    float d2a, d2b; UNPK2(d2a, d2b, d2p);
                    if (d2a < TH2) {
                        unsigned long long key =
                            ((unsigned long long)__float_as_uint(d2a) << 32) | (unsigned)j2;
                        if (key < curmax) {
                            keys[maxslot] = key;
                            curmax = keys[0]; maxslot = 0;
#pragma unroll
                            for (int k = 1; k < TK; k++)
                                if (keys[k] > curmax) { curmax = keys[k]; maxslot = k; }
                        }
                    }
                    if (d2b < TH2) {
                        unsigned long long key =
                            ((unsigned long long)__float_as_uint(d2b) << 32) | (unsigned)(j2+1);
                        if (key < curmax) {
                            keys[maxslot] = key;
                            curmax = keys[0]; maxslot = 0;
#pragma unroll
                            for (int k = 1; k < TK; k++)
                                if (keys[k] > curmax) { curmax = keys[k]; maxslot = k; }
                        }
                    }
                }
            }
#pragma unroll 1
            for (int r = 0; r < TK; r++) {
                unsigned long long mymin = keys[0]; int mslot = 0;
#pragma unroll
                for (int k = 1; k < TK; k++)
                    if (keys[k] < mymin) { mymin = keys[k]; mslot = k; }
                unsigned long long v = mymin;
#pragma unroll
                for (int off = 16; off; off >>= 1) {
                    unsigned long long o = __shfl_down_sync(0xffffffffu, v, off);
                    if (o < v) v = o;
                }
                v = __shfl_sync(0xffffffffu, v, 0);
                if (v == mymin && v != ~0ULL) keys[mslot] = ~0ULL;
                if (lane == 0) {
                    int j = (int)(v & 0xffffffffULL);
                    bool valid = (v != ~0ULL);
                    g_send[node*TK + r] = valid ? j : -1;
                }
            }
        }
        __syncthreads();
    }

    // ======== Phase P: particle encoder + hoisted q (transposed FMA2) ======
    {
        float* sw1 = buf;           // 768
        float* sw2 = buf + 768;     // 4096
        float* swq = buf + 4864;    // 4096
        float* sb1 = buf + 8960;    // 64
        float* sb2 = buf + 9024;    // 64
        float* sbq = buf + 9088;    // 64
        float* sX  = buf + 9152;    // 64*66 = 4224 -> end 13376
        for (int t = tid; t < 768;  t += NT) sw1[t] = pe_w1[t];
        for (int t = tid; t < 4096; t += NT) { sw2[t] = pe_w2[t]; swq[t] = pp_w[t]; }
        if (tid < 64) { sb1[tid]=pe_b1[tid]; sb2[tid]=pe_b2[tid]; sbq[tid]=pp_b[tid]; }
        if (tid < 384) {
            int n = tid & 31, r = tid >> 5;   // r 0..11
            int nn = (node0 + n) & (NN-1);
            float v = (r < 9) ? s_delta[((size_t)bb*9 + r)*NN + nn]
                              : a_cur[bb*NN + nn];
            *(float2*)&sX[r*66 + 2*n] = make_float2(v, v);
        }
        __syncthreads();

        int tc = tid & 15, tn = tid >> 4;   // 16 colgroups x 32 nodes
        int node = node0 + tn;
        unsigned long long acc[2];
        float hreg[4];

        // L1: 12 -> 64, relu
        PACK2(acc[0], sb1[tc*4],   sb1[tc*4+1]);
        PACK2(acc[1], sb1[tc*4+2], sb1[tc*4+3]);
#pragma unroll
        for (int r = 0; r < 12; r++) {
            unsigned long long ev = *(const unsigned long long*)&sX[r*66 + 2*tn];
            ulonglong2 w = *(const ulonglong2*)&sw1[r*64 + tc*4];
            FMA2(acc[0], w.x, ev); FMA2(acc[1], w.y, ev);
        }
        {
            float a0,a1,a2,a3; UNPK2(a0,a1,acc[0]); UNPK2(a2,a3,acc[1]);
            hreg[0]=fmaxf(a0,0.f); hreg[1]=fmaxf(a1,0.f);
            hreg[2]=fmaxf(a2,0.f); hreg[3]=fmaxf(a3,0.f);
        }
        __syncthreads();
#pragma unroll
        for (int p = 0; p < 4; p++)
            *(float2*)&sX[(tc*4+p)*66 + 2*tn] = make_float2(hreg[p], hreg[p]);
        __syncthreads();

        // L2: 64 -> 64, relu -> pe (g_eff0) + restage
        PACK2(acc[0], sb2[tc*4],   sb2[tc*4+1]);
        PACK2(acc[1], sb2[tc*4+2], sb2[tc*4+3]);
#pragma unroll 8
        for (int r = 0; r < 64; r++) {
            unsigned long long ev = *(const unsigned long long*)&sX[r*66 + 2*tn];
            ulonglong2 w = *(const ulonglong2*)&sw2[r*64 + tc*4];
            FMA2(acc[0], w.x, ev); FMA2(acc[1], w.y, ev);
        }
        {
            float a0,a1,a2,a3; UNPK2(a0,a1,acc[0]); UNPK2(a2,a3,acc[1]);
            hreg[0]=fmaxf(a0,0.f); hreg[1]=fmaxf(a1,0.f);
            hreg[2]=fmaxf(a2,0.f); hreg[3]=fmaxf(a3,0.f);
        }
        *(float4*)&g_eff0[(size_t)node*64 + tc*4] =
            make_float4(hreg[0], hreg[1], hreg[2], hreg[3]);
        __syncthreads();
#pragma unroll
        for (int p = 0; p < 4; p++)
            *(float2*)&sX[(tc*4+p)*66 + 2*tn] = make_float2(hreg[p], hreg[p]);
        __syncthreads();

        // L3: q = pe @ pp_w[0:64] + pp_b (no relu)
        PACK2(acc[0], sbq[tc*4],   sbq[tc*4+1]);
        PACK2(acc[1], sbq[tc*4+2], sbq[tc*4+3]);
#pragma unroll 8
        for (int r = 0; r < 64; r++) {
            unsigned long long ev = *(const unsigned long long*)&sX[r*66 + 2*tn];
            ulonglong2 w = *(const ulonglong2*)&swq[r*64 + tc*4];
            FMA2(acc[0], w.x, ev); FMA2(acc[1], w.y, ev);
        }
        {
            float a0,a1,a2,a3; UNPK2(a0,a1,acc[0]); UNPK2(a2,a3,acc[1]);
            *(float4*)&g_q[(size_t)node*64 + tc*4] = make_float4(a0,a1,a2,a3);
        }
        __syncthreads();
    }

    // ======== Phase R: relation encoder (4 thr/edge, 2 edges/thread) ======
    {
        float* sW2 = buf;           // 5120 (64 x stride80, chunk20)
        float* sW3 = buf + 5120;
        float* sWA = buf + 10240;
        float* sw1 = buf + 15360;   // 320
        float* sb1 = buf + 15680;
        float* sb2 = buf + 15744;
        float* sb3 = buf + 15808;
        float* sb4 = buf + 15872;
        float* sh  = buf + 15936;   // 256*132 = 33792 -> end 49728
        for (int t = tid; t < 4096; t += NT) {
            int r = t >> 6, c = t & 63;
            int off = r*80 + (c>>4)*20 + (c&15);
            sW2[off] = re_w2[t];
            sW3[off] = re_w3[t];
            sWA[off] = rp_w[t];
        }
        for (int t = tid; t < 320; t += NT) sw1[t] = re_w1[t];
        if (tid < 64) {
            sb1[tid]=re_b1[tid]; sb2[tid]=re_b2[tid];
            sb3[tid]=re_b3[tid]; sb4[tid]=rp_b[tid];
        }
        __syncthreads();

        int el = tid >> 2, part = tid & 3, cbase = part*16;  // el 0..127
        float* row0 = &sh[el*132];
        float* row1 = &sh[(128+el)*132];
        int e0 = node0*TK + el;
        int e1 = e0 + 128;
        int n0 = e0 >> 3, n1 = e1 >> 3;
        int i0e = n0 & (NN-1), i1e = n1 & (NN-1);
        int j0 = g_send[e0], j1 = g_send[e1];
        int jj0 = j0 < 0 ? 0 : j0, jj1 = j1 < 0 ? 0 : j1;

        float rin0[5], rin1[5];
        rin0[0] = a_cur[bb*NN + i0e];  rin1[0] = a_cur[bb*NN + i1e];
        rin0[1] = a_cur[bb*NN + jj0];  rin1[1] = a_cur[bb*NN + jj1];
#pragma unroll
        for (int d = 0; d < 3; d++) {
            rin0[2+d] = states[((size_t)bb*NN + i0e)*3 + d]
                      - states[((size_t)bb*NN + jj0)*3 + d];
            rin1[2+d] = states[((size_t)bb*NN + i1e)*3 + d]
                      - states[((size_t)bb*NN + jj1)*3 + d];
        }

        unsigned long long a0r[8], a1r[8];
        // ---- L1: 5 -> 64 ----
#pragma unroll
        for (int p = 0; p < 8; p++) {
            PACK2(a0r[p], sb1[cbase + 2*p], sb1[cbase + 2*p + 1]);
            a1r[p] = a0r[p];
        }
#pragma unroll
        for (int r = 0; r < 5; r++) {
            unsigned long long x0; DUP2(x0, rin0[r]);
            unsigned long long x1; DUP2(x1, rin1[r]);
            const float* wp = &sw1[r*64 + cbase];
#pragma unroll
            for (int p = 0; p < 8; p++) {
                unsigned long long wv = *(const unsigned long long*)(wp + 2*p);
                FMA2(a0r[p], wv, x0);
                FMA2(a1r[p], wv, x1);
            }
        }
        __syncwarp();
        rel_store_h(row0, cbase, a0r);
        rel_store_h(row1, cbase, a1r);
        __syncwarp();

        // ---- L2 (re_w2,relu), L3 (re_w3,relu), L4 (rp_w[0:64]+rp_b) ----
        // Software-pipelined: prefetch r+1 (over-read at r=63 stays in smem).
#pragma unroll 1
        for (int L = 0; L < 3; L++) {
            const float* Wm = (L==0) ? sW2 : (L==1) ? sW3 : sWA;
            const float* Bm = (L==0) ? sb2 : (L==1) ? sb3 : sb4;
#pragma unroll
            for (int p = 0; p < 8; p++) {
                PACK2(a0r[p], Bm[cbase + 2*p], Bm[cbase + 2*p + 1]);
                a1r[p] = a0r[p];
            }
            unsigned long long hv0 = *(const unsigned long long*)(row0);
            unsigned long long hv1 = *(const unsigned long long*)(row1);
            const float* wp0 = &Wm[part*20];
            ulonglong2 wa = *(const ulonglong2*)(wp0);
            ulonglong2 wb = *(const ulonglong2*)(wp0 + 4);
            ulonglong2 wc = *(const ulonglong2*)(wp0 + 8);
            ulonglong2 wd = *(const ulonglong2*)(wp0 + 12);
#pragma unroll 8
            for (int r = 0; r < 64; r++) {
                unsigned long long nh0 =
                    *(const unsigned long long*)(row0 + 2*(r+1));
                unsigned long long nh1 =
                    *(const unsigned long long*)(row1 + 2*(r+1));
                const float* wp = &Wm[(r+1)*80 + part*20];
                ulonglong2 na = *(const ulonglong2*)(wp);
                ulonglong2 nb = *(const ulonglong2*)(wp + 4);
                ulonglong2 nc = *(const ulonglong2*)(wp + 8);
                ulonglong2 nd = *(const ulonglong2*)(wp + 12);
                FMA2(a0r[0], wa.x, hv0); FMA2(a0r[1], wa.y, hv0);
                FMA2(a0r[2], wb.x, hv0); FMA2(a0r[3], wb.y, hv0);
                FMA2(a0r[4], wc.x, hv0); FMA2(a0r[5], wc.y, hv0);
                FMA2(a0r[6], wd.x, hv0); FMA2(a0r[7], wd.y, hv0);
                FMA2(a1r[0], wa.x, hv1); FMA2(a1r[1], wa.y, hv1);
                FMA2(a1r[2], wb.x, hv1); FMA2(a1r[3], wb.y, hv1);
                FMA2(a1r[4], wc.x, hv1); FMA2(a1r[5], wc.y, hv1);
                FMA2(a1r[6], wd.x, hv1); FMA2(a1r[7], wd.y, hv1);
                hv0 = nh0; hv1 = nh1;
                wa = na; wb = nb; wc = nc; wd = nd;
            }
            if (L < 2) {
                __syncwarp();
                rel_store_h(row0, cbase, a0r);
                rel_store_h(row1, cbase, a1r);
                __syncwarp();
            } else {
                // all sh reads done -> overlay A region (overlaps sh tail)
                __syncthreads();
                float* dst0 = sA + (size_t)el*SAA + cbase;
                float* dst1 = sA + (size_t)(128+el)*SAA + cbase;
#pragma unroll
                for (int p = 0; p < 4; p++) {
                    float a0,a1,a2,a3;
                    UNPK2(a0, a1, a0r[2*p]);
                    UNPK2(a2, a3, a0r[2*p+1]);
                    if (j0 < 0) { a0 = a1 = a2 = a3 = 0.f; }
                    *(float4*)(dst0 + 4*p) = make_float4(a0, a1, a2, a3);
                    UNPK2(a0, a1, a1r[2*p]);
                    UNPK2(a2, a3, a1r[2*p+1]);
                    if (j1 < 0) { a0 = a1 = a2 = a3 = 0.f; }
                    *(float4*)(dst1 + 4*p) = make_float4(a0, a1, a2, a3);
                }
            }
        }
        __syncthreads();
    }

    // ======== Phase S: UV0 + 3 fused prop steps ========
    {
        float* sWp  = buf;            // 4096 (pp_w rows 64..127)
        float* sWrs = buf + 4096;     // 12288 ([Wr|Ws] chunk-padded)
        float* sAgg = buf + 16384;    // 64*SA = 4224
        float* sEd  = buf + 20608;    // 64*SED = 4224 -> end 24832 (sA follows)
        for (int t = tid; t < 4096; t += NT) sWp[t] = pp_w[4096 + t];
        for (int t = tid; t < 8192; t += NT) {
            int r = t >> 7, c = t & 127;
            float v = (c < 64) ? rp_w[(size_t)(64+r)*64 + c]
                               : rp_w[(size_t)(128+r)*64 + (c-64)];
            sWrs[r*192 + (c>>3)*12 + (c&7)] = v;
        }
        // fill sEd from eff0 (own nodes), duplicated-transposed
        {
            int n = tid >> 4, cg = tid & 15;   // n 0..31, 4 cols each
            const float* src = g_eff0 + (size_t)(node0 + n)*64 + cg*4;
            float4 v = *(const float4*)src;
            int c = cg*4;
            *(float2*)&sEd[(c+0)*SED + 2*n] = make_float2(v.x, v.x);
            *(float2*)&sEd[(c+1)*SED + 2*n] = make_float2(v.y, v.y);
            *(float2*)&sEd[(c+2)*SED + 2*n] = make_float2(v.z, v.z);
            *(float2*)&sEd[(c+3)*SED + 2*n] = make_float2(v.w, v.w);
        }
        __syncthreads();
        uv_from_sEd(sWrs, sEd, node0, tid);   // UV0
        grid_bar();

#pragma unroll 1
        for (int s = 0; s < 3; s++) {
            const float* effin  = (s & 1) ? g_eff1 : g_eff0;
            float*       effout = (s & 1) ? g_eff0 : g_eff1;

            // --- A1: per-edge gather + relu-sum -> sAgg (batched, MLP 8) ---
            int w = tid >> 5, l = tid & 31;   // w 0..15
#pragma unroll 1
            for (int kk = 0; kk < 2; kk++) {
                int node = node0 + w*2 + kk;
                int nl = node - node0;
                int nl8 = nl * TK;
                int bN = bb * NN;
                int4 sj0 = *(const int4*)&g_send[node*TK];
                int4 sj1 = *(const int4*)&g_send[node*TK + 4];
                int js[TK] = {sj0.x, sj0.y, sj0.z, sj0.w,
                              sj1.x, sj1.y, sj1.z, sj1.w};
                float2 u = *(const float2*)&g_UV[(size_t)node*128 + 2*l];
                float2 av[TK], vv[TK];
#pragma unroll
                for (int k = 0; k < TK; k++) {
                    int jj = js[k] < 0 ? 0 : js[k];
                    av[k] = *(const float2*)&sA[(size_t)(nl8 + k)*SAA + 2*l];
                    vv[k] = *(const float2*)&g_UV[(size_t)(bN + jj)*128 + 64 + 2*l];
                }
                float s0 = 0.f, s1 = 0.f;
#pragma unroll
                for (int k = 0; k < TK; k++)
                    if (js[k] >= 0) {
                        s0 += fmaxf(av[k].x + u.x + vv[k].x, 0.f);
                        s1 += fmaxf(av[k].y + u.y + vv[k].y, 0.f);
                    }
                *(float2*)&sAgg[(2*l  )*SA + 2*nl] = make_float2(s0, s0);
                *(float2*)&sAgg[(2*l+1)*SA + 2*nl] = make_float2(s1, s1);
            }
            __syncthreads();

            // --- A2: effout = relu(effin + q + agg @ Wp1) ; refill sEd ---
            {
                int tc = tid & 31;   // 2 cols
                int tn = tid >> 5;   // 0..15, 2 nodes each
                unsigned long long acc[2] = {0ULL, 0ULL};
                unsigned long long wv =
                    *(const unsigned long long*)&sWp[tc*2];
                unsigned long long ev0 =
                    *(const unsigned long long*)&sAgg[tn*4];
                unsigned long long ev1 =
                    *(const unsigned long long*)&sAgg[tn*4 + 2];
#pragma unroll 8
                for (int r = 0; r < 64; r++) {
                    unsigned long long nw =
                        *(const unsigned long long*)&sWp[(r+1)*64 + tc*2];
                    unsigned long long n0 =
                        *(const unsigned long long*)&sAgg[(r+1)*SA + tn*4];
                    unsigned long long n1 =
                        *(const unsigned long long*)&sAgg[(r+1)*SA + tn*4 + 2];
                    FMA2(acc[0], wv, ev0);
                    FMA2(acc[1], wv, ev1);
                    wv = nw; ev0 = n0; ev1 = n1;
                }
#pragma unroll
                for (int m = 0; m < 2; m++) {
                    int node = node0 + tn*2 + m;
                    int nl = tn*2 + m;
                    float2 ein = *(const float2*)&effin[(size_t)node*64 + 2*tc];
                    float2 q2  = *(const float2*)&g_q  [(size_t)node*64 + 2*tc];
                    float o0, o1; UNPK2(o0, o1, acc[m]);
                    o0 = fmaxf(o0 + ein.x + q2.x, 0.f);
                    o1 = fmaxf(o1 + ein.y + q2.y, 0.f);
                    *(float2*)&effout[(size_t)node*64 + 2*tc] = make_float2(o0, o1);
                    *(float2*)&sEd[(2*tc  )*SED + 2*nl] = make_float2(o0, o0);
                    *(float2*)&sEd[(2*tc+1)*SED + 2*nl] = make_float2(o1, o1);
                }
            }
            if (s < 2) {
                __syncthreads();
                uv_from_sEd(sWrs, sEd, node0, tid);  // UV for next step
                grid_bar();
            }
        }
        __syncthreads();
    }

    // ======== Phase D: predictor + residual add (from sEd, FMA2) ========
    {
        float* W1   = buf;          // 4096
        float* W2   = buf + 4096;   // 192
        float* b1   = buf + 4288;   // 64
        float* b2   = buf + 4352;   // 4
        float* sHH  = buf + 16384;  // hh staging, stride SA
        float* sEd  = buf + 20608;  // final effect (dup transposed)
        for (int t = tid; t < 4096; t += NT) W1[t] = pr_w1[t];
        for (int t = tid; t < 192;  t += NT) W2[t] = pr_w2[t];
        if (tid < 64) b1[tid] = pr_b1[tid];
        if (tid < 3)  b2[tid] = pr_b2[tid];
        __syncthreads();

        // layer 1: hh = relu(eff @ W1 + b1); sHH[r*SA + n] = hh[n][r]
        {
            int tc = tid & 31;   // 2 cols
            int tn = tid >> 5;   // 0..15, 2 nodes each
#pragma unroll
            for (int m = 0; m < 2; m++) {
                int nl = tn*2 + m;
                unsigned long long acc;
                PACK2(acc, b1[2*tc], b1[2*tc+1]);
#pragma unroll 8
                for (int r = 0; r < 64; r++) {
                    unsigned long long wv =
                        *(const unsigned long long*)&W1[r*64 + tc*2];
                    unsigned long long ev =
                        *(const unsigned long long*)&sEd[r*SED + 2*nl];
                    FMA2(acc, wv, ev);
                }
                float o0, o1; UNPK2(o0, o1, acc);
                sHH[(2*tc  )*SA + nl] = fmaxf(o0, 0.f);
                sHH[(2*tc+1)*SA + nl] = fmaxf(o1, 0.f);
            }
        }
        __syncthreads();

        // layer 2: out = states + hh @ W2 + b2  (3 cols, 96 workers)
        if (tid < 96) {
            int n = tid / 3, c = tid % 3;
            float acc = b2[c];
#pragma unroll 16
            for (int r = 0; r < 64; r++)
                acc = fmaf(sHH[r*SA + n], W2[r*3 + c], acc);
            int node = node0 + n;
            out[(size_t)node*3 + c] = states[(size_t)node*3 + c] + acc;
        }
    }
}

// ---------------- launch ----------------
extern "C" void kernel_launch(void* const* d_in, const int* in_sizes, int n_in,
                              void* d_out, int out_size)
{
    const float* states  = (const float*)d_in[0];
    const float* a_cur   = (const float*)d_in[1];
    const float* s_delta = (const float*)d_in[2];
    const unsigned char* mask  = (const unsigned char*)d_in[3];
    const unsigned char* tmask = (const unsigned char*)d_in[4];
    int wbase = (n_in > 5 && in_sizes[5] == 1) ? 6 : 5;
    const float* pe_w1 = (const float*)d_in[wbase + 0];
    const float* pe_b1 = (const float*)d_in[wbase + 1];
    const float* pe_w2 = (const float*)d_in[wbase + 2];
    const float* pe_b2 = (const float*)d_in[wbase + 3];
    const float* re_w1 = (const float*)d_in[wbase + 4];
    const float* re_b1 = (const float*)d_in[wbase + 5];
    const float* re_w2 = (const float*)d_in[wbase + 6];
    const float* re_b2 = (const float*)d_in[wbase + 7];
    const float* re_w3 = (const float*)d_in[wbase + 8];
    const float* re_b3 = (const float*)d_in[wbase + 9];
    const float* rp_w  = (const float*)d_in[wbase + 10];
    const float* rp_b  = (const float*)d_in[wbase + 11];
    const float* pp_w  = (const float*)d_in[wbase + 12];
    const float* pp_b  = (const float*)d_in[wbase + 13];
    const float* pr_w1 = (const float*)d_in[wbase + 14];
    const float* pr_b1 = (const float*)d_in[wbase + 15];
    const float* pr_w2 = (const float*)d_in[wbase + 16];
    const float* pr_b2 = (const float*)d_in[wbase + 17];
    float* out = (float*)d_out;

    const int DSM = 49728 * 4;   // 198912 B (phase R peak)
    static int attr_done = 0;
    if (!attr_done) {
        cudaFuncSetAttribute(k_all, cudaFuncAttributeMaxDynamicSharedMemorySize, DSM);
        attr_done = 1;
    }

    k_all<<<NBLK, NT, DSM>>>(states, a_cur, s_delta, mask, tmask,
                             pe_w1, pe_b1, pe_w2, pe_b2,
                             re_w1, re_b1, re_w2, re_b2, re_w3, re_b3,
                             rp_w, rp_b, pp_w, pp_b,
                             pr_w1, pr_b1, pr_w2, pr_b2, out);
}